// round 15
// baseline (speedup 1.0000x reference)
#include <cuda_runtime.h>
#include <cuda_fp16.h>
#include <math.h>
#include <stdint.h>

#define B_TOK 16384
#define D_DIM 1024
#define H_DIM 256
#define E_NUM 8
#define NPAIR 28
#define TM    64
#define TM2   128
#define NTHR  256

#define E1_TILES (B_TOK * 2 / TM + E_NUM)     // 520
#define E2_TILES (B_TOK / TM2 + NPAIR)        // 156

// e1 smem: 2-stage ring, stage = A(8KB) + B(32KB)
#define ST_SZ   40960
#define ST_B    8192
#define DYN_SMEM 81920

// e2 smem: 3-stage ring, stage = A(16KB) + B(32KB) = 48KB
#define ST2_SZ  49152
#define ST2_B   16384
#define DYN_SMEM2 147456

// gate smem: gws 32KB @0, x stages 2 x 28KB @32768
#define GATE_BLKS 293
#define GATE_TOK  56
#define GATE_STG  28672
#define GATE_DYN  (32768 + 2 * GATE_STG)

// ---------------- device scratch ----------------
__device__ int    g_cnt[E_NUM];
__device__ int    g_pc[NPAIR];
__device__ int    g_e1pre[E_NUM + 1];
__device__ int    g_e2pre[NPAIR + 1];
__device__ int    g_tok[E_NUM][B_TOK];
__device__ float  g_wgt[E_NUM][B_TOK];
__device__ int4   g_plist[NPAIR][B_TOK];        // {tok, slot_a, slot_b, 0}
__device__ float2 g_pwt[NPAIR][B_TOK];
__device__ __half g_xh[(size_t)B_TOK * D_DIM];
__device__ __half g_w1h[(size_t)E_NUM * H_DIM * D_DIM];
__device__ __half g_w2h[(size_t)E_NUM * D_DIM * H_DIM];
__device__ __half g_h[(size_t)E_NUM * B_TOK * H_DIM];   // wt*gelu(h) fp16

__constant__ int c_pa[NPAIR] = {0,0,0,0,0,0,0, 1,1,1,1,1,1, 2,2,2,2,2, 3,3,3,3, 4,4,4, 5,5, 6};
__constant__ int c_pb[NPAIR] = {1,2,3,4,5,6,7, 2,3,4,5,6,7, 3,4,5,6,7, 4,5,6,7, 5,6,7, 6,7, 7};

// ---------------- helpers ----------------
__device__ __forceinline__ uint32_t smem_u32(const void* p) {
    uint32_t r;
    asm("{.reg .u64 t; cvta.to.shared.u64 t,%1; cvt.u32.u64 %0,t;}" : "=r"(r) : "l"(p));
    return r;
}
__device__ __forceinline__ void cp16(uint32_t s, const void* g) {
    asm volatile("cp.async.cg.shared.global [%0],[%1],16;" :: "r"(s), "l"(g));
}
__device__ __forceinline__ void cp_commit() {
    asm volatile("cp.async.commit_group;" ::: "memory");
}
template <int N> __device__ __forceinline__ void cp_wait() {
    asm volatile("cp.async.wait_group %0;" :: "n"(N) : "memory");
}
__device__ __forceinline__ void mbar_init(uint32_t mb, uint32_t cnt) {
    asm volatile("mbarrier.init.shared.b64 [%0], %1;" :: "r"(mb), "r"(cnt) : "memory");
}
__device__ __forceinline__ void mbar_expect(uint32_t mb, uint32_t bytes) {
    asm volatile("mbarrier.arrive.expect_tx.shared.b64 _, [%0], %1;"
                 :: "r"(mb), "r"(bytes) : "memory");
}
__device__ __forceinline__ void bulk_g2s(uint32_t dst, const void* src,
                                         uint32_t bytes, uint32_t mb) {
    asm volatile(
        "cp.async.bulk.shared::cluster.global.mbarrier::complete_tx::bytes "
        "[%0], [%1], %2, [%3];"
        :: "r"(dst), "l"(src), "r"(bytes), "r"(mb) : "memory");
}
__device__ __forceinline__ void mbar_wait(uint32_t mb, uint32_t ph) {
    asm volatile(
        "{.reg .pred P;\n\t"
        "WL%=:\n\t"
        "mbarrier.try_wait.parity.acquire.cta.shared::cta.b64 P,[%0],%1,0x989680;\n\t"
        "@P bra WD%=;\n\t"
        "bra WL%=;\n\t"
        "WD%=:}" :: "r"(mb), "r"(ph) : "memory");
}
__device__ __forceinline__ void ldsm4(uint32_t* r, uint32_t a) {
    asm volatile("ldmatrix.sync.aligned.m8n8.x4.shared.b16 {%0,%1,%2,%3},[%4];"
                 : "=r"(r[0]), "=r"(r[1]), "=r"(r[2]), "=r"(r[3]) : "r"(a));
}
__device__ __forceinline__ void mma16(float* c, const uint32_t* a, const uint32_t* b) {
    asm volatile(
        "mma.sync.aligned.m16n8k16.row.col.f32.f16.f16.f32 "
        "{%0,%1,%2,%3},{%4,%5,%6,%7},{%8,%9},{%0,%1,%2,%3};"
        : "+f"(c[0]), "+f"(c[1]), "+f"(c[2]), "+f"(c[3])
        : "r"(a[0]), "r"(a[1]), "r"(a[2]), "r"(a[3]), "r"(b[0]), "r"(b[1]));
}

// ---------------- weight prep (merged): [E][K][N] fp32 -> [e][k/64][n][64] fp16 swizzled ----------------
__global__ void prep_w_kernel(const float* __restrict__ w1, const float* __restrict__ w2,
                              __half* __restrict__ d1, __half* __restrict__ d2) {
    __shared__ float tile[64][33];
    if (blockIdx.x == 0 && blockIdx.z == 0 && threadIdx.y == 0) {
        if (threadIdx.x < E_NUM) g_cnt[threadIdx.x] = 0;
        if (threadIdx.x < NPAIR) g_pc[threadIdx.x] = 0;
    }
    const int z = blockIdx.z;
    const bool is1 = z < E_NUM;
    const int e = is1 ? z : z - E_NUM;
    const int f = blockIdx.x;
    const int K = is1 ? D_DIM : H_DIM;
    const int N = is1 ? H_DIM : D_DIM;
    const int s  = is1 ? (f >> 3) : (f >> 5);
    const int n0 = (is1 ? (f & 7) : (f & 31)) * 32;
    const float* src = is1 ? w1 : w2;
    __half*      dst = is1 ? d1 : d2;

    const int tx = threadIdx.x, ty = threadIdx.y;      // 32 x 8
    const float* sp = src + (size_t)e * K * N + (size_t)s * 64 * N + n0;
#pragma unroll
    for (int dy = 0; dy < 8; dy++)
        tile[ty + dy * 8][tx] = sp[(size_t)(ty + dy * 8) * N + tx];
    __syncthreads();
    __half* dp = dst + (((size_t)e * (K / 64) + s) * N + n0) * 64;
    const int nn = n0 + tx;
#pragma unroll
    for (int dy = 0; dy < 4; dy++) {
        int k = (ty + dy * 8) * 2;
        __half2 v = __floats2half2_rn(tile[k][tx], tile[k + 1][tx]);
        *(__half2*)(dp + (size_t)tx * 64 + (((k >> 3) ^ (nn & 7)) << 3) + (k & 7)) = v;
    }
}

// ---------------- gate v3: cp.async-staged, single wave, 2 CTA/SM ----------------
__global__ __launch_bounds__(512) void gate_kernel(
    const float* __restrict__ x, const float* __restrict__ gw,
    const float* __restrict__ gb)
{
    extern __shared__ __align__(16) float gsm[];       // gws @0, stages @8192 floats
    const int tid = threadIdx.x;

    for (int k = tid; k < D_DIM; k += 512) {
        float4 a = *(const float4*)(gw + k * 8);
        float4 b = *(const float4*)(gw + k * 8 + 4);
        gsm[0 * D_DIM + k] = a.x; gsm[1 * D_DIM + k] = a.y;
        gsm[2 * D_DIM + k] = a.z; gsm[3 * D_DIM + k] = a.w;
        gsm[4 * D_DIM + k] = b.x; gsm[5 * D_DIM + k] = b.y;
        gsm[6 * D_DIM + k] = b.z; gsm[7 * D_DIM + k] = b.w;
    }

    const int tok_base = blockIdx.x * GATE_TOK;
    const uint32_t stg = smem_u32(gsm) + 32768;

    auto stage = [&](int j, int buf) {
        const uint32_t db = stg + buf * GATE_STG;
#pragma unroll
        for (int t = 0; t < 4; t++) {
            int i = tid + t * 512;
            if (i < GATE_TOK * 32) {
                int r = i >> 5, u = i & 31;
                int tok = tok_base + r;
                if (tok < B_TOK)
                    cp16(db + i * 16, x + (size_t)tok * D_DIM + j * 128 + u * 4);
            }
        }
        cp_commit();
    };

    stage(0, 0);
    stage(1, 1);

    const int warp = tid >> 5, lane = tid & 31;
    const int t0 = tok_base + warp * 4;
    const int d0 = lane * 4;

    float acc[4][E_NUM];
#pragma unroll
    for (int t = 0; t < 4; t++)
#pragma unroll
        for (int e = 0; e < E_NUM; e++) acc[t][e] = 0.f;

    for (int j = 0; j < 8; j++) {
        const int buf = j & 1;
        if (j < 6) cp_wait<1>(); else cp_wait<0>();
        __syncthreads();
        if (warp < 14) {
            const float* xsb = gsm + 8192 + buf * (GATE_STG / 4);
            const int dj = j * 128 + d0;
#pragma unroll
            for (int t = 0; t < 4; t++) {
                float4 cur = *(const float4*)&xsb[(warp * 4 + t) * 128 + d0];
#pragma unroll
                for (int e = 0; e < E_NUM; e++) {
                    const float4 wv = *(const float4*)&gsm[e * D_DIM + dj];
                    acc[t][e] += cur.x * wv.x + cur.y * wv.y
                               + cur.z * wv.z + cur.w * wv.w;
                }
                if (t0 + t < B_TOK) {
                    __half2 h0 = __floats2half2_rn(cur.x, cur.y);
                    __half2 h1 = __floats2half2_rn(cur.z, cur.w);
                    uint2 u = make_uint2(*(uint32_t*)&h0, *(uint32_t*)&h1);
                    *(uint2*)(g_xh + (size_t)(t0 + t) * D_DIM + dj) = u;
                }
            }
        }
        __syncthreads();
        if (j + 2 < 8) stage(j + 2, buf);
    }

    if (warp >= 14) return;

#pragma unroll
    for (int t = 0; t < 4; t++)
#pragma unroll
        for (int e = 0; e < E_NUM; e++)
#pragma unroll
            for (int s = 16; s; s >>= 1)
                acc[t][e] += __shfl_xor_sync(0xffffffffu, acc[t][e], s);

    if (lane == 0) {
#pragma unroll
        for (int t = 0; t < 4; t++) {
            if (t0 + t >= B_TOK) break;
            float l[E_NUM];
#pragma unroll
            for (int e = 0; e < E_NUM; e++) l[e] = acc[t][e] + gb[e];
            int i0 = 0;
#pragma unroll
            for (int e = 1; e < E_NUM; e++) if (l[e] > l[i0]) i0 = e;
            int i1 = (i0 == 0) ? 1 : 0;
#pragma unroll
            for (int e = 0; e < E_NUM; e++) if (e != i0 && l[e] > l[i1]) i1 = e;
            float e1 = expf(l[i1] - l[i0]);
            float s  = 1.0f + e1;
            float wv0 = 1.0f / s, wv1 = e1 / s;
            int tok  = t0 + t;
            int p0 = atomicAdd(&g_cnt[i0], 1);
            g_tok[i0][p0] = tok; g_wgt[i0][p0] = wv0;
            int p1 = atomicAdd(&g_cnt[i1], 1);
            g_tok[i1][p1] = tok; g_wgt[i1][p1] = wv1;
            int a = min(i0, i1), b = max(i0, i1);
            int pidx = a * (2 * E_NUM - a - 1) / 2 + (b - a - 1);
            int pa = (a == i0) ? p0 : p1;
            int pb = (a == i0) ? p1 : p0;
            float wA = (a == i0) ? wv0 : wv1;
            float wB = (a == i0) ? wv1 : wv0;
            int pp = atomicAdd(&g_pc[pidx], 1);
            g_plist[pidx][pp] = make_int4(tok, pa, pb, 0);
            g_pwt[pidx][pp]   = make_float2(wA, wB);
        }
    }
}

// ---------------- sched: prefix sums of tile counts ----------------
__global__ void sched_kernel() {
    if (threadIdx.x == 0) {
        int s = 0;
        g_e1pre[0] = 0;
        for (int e = 0; e < E_NUM; e++) {
            s += (g_cnt[e] + TM - 1) / TM;
            g_e1pre[e + 1] = s;
        }
        s = 0;
        g_e2pre[0] = 0;
        for (int p = 0; p < NPAIR; p++) {
            s += (g_pc[p] + TM2 - 1) / TM2;
            g_e2pre[p + 1] = s;
        }
    }
}

// ---------------- E1: g_h = wt * gelu(x[64,1024] @ w1^T + b1), fp16 ----------------
__global__ void __launch_bounds__(NTHR, 2) expert1_kernel(const float* __restrict__ b1)
{
    int e = 0;
    {
        const int flat = blockIdx.x;
        if (flat >= g_e1pre[E_NUM]) return;
#pragma unroll
        for (int k = 1; k < E_NUM; k++) if (flat >= g_e1pre[k]) e = k;
    }
    const int cnt   = g_cnt[e];
    const int start = (blockIdx.x - g_e1pre[e]) * TM;

    __shared__ int   tids_s[TM];
    __shared__ float wts_s[TM];
    __shared__ __align__(8) uint64_t mbar_s[2];
    extern __shared__ __align__(16) char smem[];
    const uint32_t sb = smem_u32(smem);

    const int tid = threadIdx.x;
    if (tid < TM) {
        bool v = tid < cnt - start;
        int  src = v ? (start + tid) : start;
        tids_s[tid] = g_tok[e][src];
        wts_s[tid]  = v ? g_wgt[e][src] : 0.f;
    }
    const uint32_t mb[2] = { smem_u32(&mbar_s[0]), smem_u32(&mbar_s[1]) };
    if (tid == 0) { mbar_init(mb[0], 1); mbar_init(mb[1], 1); }
    __syncthreads();

    const int warp = tid >> 5, lane = tid & 31;
    const int wm = warp & 1, wn = warp >> 1;
    const int sub = lane >> 3, rin = lane & 7;
    const int g = lane >> 2, tg = lane & 3;
    const int arl = (sub & 1) * 8 + rin, auo = sub >> 1;
    const int brl = ((sub >> 1) & 1) * 8 + rin, buo = sub & 1;

    const __half* w1h = g_w1h + (size_t)e * 16 * 16384;
    const float*  b1e = b1 + e * H_DIM;

    const int r0 = tid >> 2, u0 = tid & 3, u1 = u0 + 4;
    const __half* ga0 = g_xh + (size_t)tids_s[r0] * D_DIM + u0 * 8;
    const __half* ga1 = g_xh + (size_t)tids_s[r0] * D_DIM + u1 * 8;
    const uint32_t sa0 = r0 * 128 + ((u0 ^ (r0 & 7)) << 4);
    const uint32_t sa1 = r0 * 128 + ((u1 ^ (r0 & 7)) << 4);

    float c[2][8][4];
#pragma unroll
    for (int mi = 0; mi < 2; mi++)
#pragma unroll
        for (int ni = 0; ni < 8; ni++)
#pragma unroll
            for (int q = 0; q < 4; q++) c[mi][ni][q] = 0.f;

    int ph[2] = {0, 0};

    if (tid == 0) { mbar_expect(mb[0], 32768); bulk_g2s(sb + ST_B, w1h, 32768, mb[0]); }
    cp16(sb + sa0, ga0); cp16(sb + sa1, ga1); cp_commit();

    for (int i = 0; i < 16; i++) {
        const int b = i & 1;
        cp_wait<0>();
        mbar_wait(mb[b], ph[b]); ph[b] ^= 1;
        __syncthreads();
        if (i + 1 < 16) {
            const int nb = b ^ 1;
            const uint32_t st = sb + nb * ST_SZ;
            if (tid == 0) {
                mbar_expect(mb[nb], 32768);
                bulk_g2s(st + ST_B, w1h + (size_t)(i + 1) * 16384, 32768, mb[nb]);
            }
            cp16(st + sa0, ga0 + (i + 1) * 64);
            cp16(st + sa1, ga1 + (i + 1) * 64);
            cp_commit();
        }
        const uint32_t Ab = sb + b * ST_SZ;
        const uint32_t Bb = Ab + ST_B;
#pragma unroll
        for (int kk = 0; kk < 4; kk++) {
            uint32_t a[2][4], bf[4][4];
#pragma unroll
            for (int mi = 0; mi < 2; mi++) {
                int row = wm * 32 + mi * 16 + arl;
                int u   = 2 * kk + auo;
                ldsm4(a[mi], Ab + row * 128 + ((u ^ (row & 7)) << 4));
            }
#pragma unroll
            for (int p = 0; p < 4; p++) {
                int row = wn * 64 + p * 16 + brl;
                int u   = 2 * kk + buo;
                ldsm4(bf[p], Bb + row * 128 + ((u ^ (row & 7)) << 4));
            }
#pragma unroll
            for (int mi = 0; mi < 2; mi++)
#pragma unroll
                for (int ni = 0; ni < 8; ni++)
                    mma16(c[mi][ni], a[mi], &bf[ni >> 1][(ni & 1) * 2]);
        }
    }
    __syncthreads();   // ring dead; reuse as staging [64][272] halves

#pragma unroll
    for (int mi = 0; mi < 2; mi++) {
#pragma unroll
        for (int ni = 0; ni < 8; ni++) {
            int col = wn * 64 + ni * 8 + tg * 2;
            float bb0 = b1e[col], bb1 = b1e[col + 1];
#pragma unroll
            for (int h = 0; h < 2; h++) {
                int row = wm * 32 + mi * 16 + g + h * 8;
                float wt = wts_s[row];
                float v0 = c[mi][ni][h * 2]     + bb0;
                float v1 = c[mi][ni][h * 2 + 1] + bb1;
                v0 = wt * (0.5f * v0 * (1.0f + erff(v0 * 0.70710678f)));
                v1 = wt * (0.5f * v1 * (1.0f + erff(v1 * 0.70710678f)));
                __half2 hv = __floats2half2_rn(v0, v1);
                asm volatile("st.shared.b32 [%0],%1;"
                             :: "r"(sb + (row * 272 + col) * 2), "r"(*(uint32_t*)&hv));
            }
        }
    }
    __syncthreads();

    __half* hdst = g_h + ((size_t)e * B_TOK + start) * H_DIM;
#pragma unroll
    for (int t = 0; t < 8; t++) {
        int ch = tid + t * NTHR;
        int row = ch >> 5, c4 = ch & 31;
        uint4 v;
        asm volatile("ld.shared.v4.b32 {%0,%1,%2,%3},[%4];"
                     : "=r"(v.x), "=r"(v.y), "=r"(v.z), "=r"(v.w)
                     : "r"(sb + row * 544 + c4 * 16));
        *(uint4*)(hdst + (size_t)row * H_DIM + c4 * 8) = v;
    }
}

// ---------------- E2: pair-bucketed K=512 GEMM, TM2=128, 16 warps, 3-stage ring ----------------
__global__ void __launch_bounds__(512, 1) expert2_kernel(
    const float* __restrict__ b2, float* __restrict__ out)
{
    int p = 0;
    {
        const int flat = blockIdx.x;
        if (flat >= g_e2pre[NPAIR]) return;
#pragma unroll
        for (int k = 1; k < NPAIR; k++) if (flat >= g_e2pre[k]) p = k;
    }
    const int py    = blockIdx.y;
    const int cnt   = g_pc[p];
    const int start = (blockIdx.x - g_e2pre[p]) * TM2;
    const int mcount = min(TM2, cnt - start);
    const int ea = c_pa[p], eb = c_pb[p];

    __shared__ int   tok_s[TM2];
    __shared__ int   pa_s[TM2], pb_s[TM2];
    __shared__ float wA_s[TM2], wB_s[TM2];
    __shared__ __align__(8) uint64_t mbar_s[3];
    extern __shared__ __align__(16) char smem[];
    const uint32_t sb = smem_u32(smem);

    const int tid = threadIdx.x;
    if (tid < TM2) {
        bool v = tid < mcount;
        int  q = v ? (start + tid) : start;
        int4 pl = g_plist[p][q];
        float2 pw = g_pwt[p][q];
        tok_s[tid] = pl.x;
        pa_s[tid]  = pl.y;
        pb_s[tid]  = pl.z;
        wA_s[tid]  = v ? pw.x : 0.f;
        wB_s[tid]  = v ? pw.y : 0.f;
    }
    const uint32_t mb[3] = { smem_u32(&mbar_s[0]), smem_u32(&mbar_s[1]),
                             smem_u32(&mbar_s[2]) };
    if (tid == 0) { mbar_init(mb[0], 1); mbar_init(mb[1], 1); mbar_init(mb[2], 1); }
    __syncthreads();

    const int warp = tid >> 5, lane = tid & 31;
    const int wm = warp & 3, wn = warp >> 2;            // 4(M,32) x 4(N,64)
    const int sub = lane >> 3, rin = lane & 7;
    const int g = lane >> 2, tg = lane & 3;
    const int arl = (sub & 1) * 8 + rin, auo = sub >> 1;
    const int brl = ((sub >> 1) & 1) * 8 + rin, buo = sub & 1;

    const __half* w2a = g_w2h + (size_t)ea * 4 * 65536 + (size_t)py * 256 * 64;
    const __half* w2b = g_w2h + (size_t)eb * 4 * 65536 + (size_t)py * 256 * 64;
    const float*  b2a = b2 + ea * D_DIM + py * 256;
    const float*  b2b = b2 + eb * D_DIM + py * 256;

    const int r0 = tid >> 2, u0 = tid & 3, u1 = u0 + 4;   // 128 rows x {u0,u1}
    const __half* hA0 = g_h + ((size_t)ea * B_TOK + pa_s[r0]) * H_DIM + u0 * 8;
    const __half* hA1 = g_h + ((size_t)ea * B_TOK + pa_s[r0]) * H_DIM + u1 * 8;
    const __half* hB0 = g_h + ((size_t)eb * B_TOK + pb_s[r0]) * H_DIM + u0 * 8;
    const __half* hB1 = g_h + ((size_t)eb * B_TOK + pb_s[r0]) * H_DIM + u1 * 8;
    const uint32_t sa0 = r0 * 128 + ((u0 ^ (r0 & 7)) << 4);
    const uint32_t sa1 = r0 * 128 + ((u1 ^ (r0 & 7)) << 4);

    float c[2][8][4];
#pragma unroll
    for (int mi = 0; mi < 2; mi++)
#pragma unroll
        for (int ni = 0; ni < 8; ni++)
#pragma unroll
            for (int q = 0; q < 4; q++) c[mi][ni][q] = 0.f;

    int ph[3] = {0, 0, 0};

    auto issue = [&](int sl) {                          // slice sl -> stage sl%3
        const uint32_t st = sb + (sl % 3) * ST2_SZ;
        const __half* ws = (sl < 4) ? (w2a + (size_t)sl * 65536)
                                    : (w2b + (size_t)(sl - 4) * 65536);
        if (tid == 0) { mbar_expect(mb[sl % 3], 32768); bulk_g2s(st + ST2_B, ws, 32768, mb[sl % 3]); }
        const __half* s0 = (sl < 4) ? (hA0 + sl * 64) : (hB0 + (sl - 4) * 64);
        const __half* s1 = (sl < 4) ? (hA1 + sl * 64) : (hB1 + (sl - 4) * 64);
        cp16(st + sa0, s0);
        cp16(st + sa1, s1);
        cp_commit();
    };

    issue(0);
    issue(1);

    for (int i = 0; i < 8; i++) {
        const int b = i % 3;
        if (i < 7) cp_wait<1>(); else cp_wait<0>();
        mbar_wait(mb[b], ph[b]); ph[b] ^= 1;
        __syncthreads();
        if (i + 2 < 8) issue(i + 2);
        const uint32_t Ab = sb + b * ST2_SZ;
        const uint32_t Bb = Ab + ST2_B;
#pragma unroll
        for (int kk = 0; kk < 4; kk++) {
            uint32_t a[2][4], bf[4][4];
#pragma unroll
            for (int mi = 0; mi < 2; mi++) {
                int row = wm * 32 + mi * 16 + arl;
                int u   = 2 * kk + auo;
                ldsm4(a[mi], Ab + row * 128 + ((u ^ (row & 7)) << 4));
            }
#pragma unroll
            for (int q = 0; q < 4; q++) {
                int row = wn * 64 + q * 16 + brl;
                int u   = 2 * kk + buo;
                ldsm4(bf[q], Bb + row * 128 + ((u ^ (row & 7)) << 4));
            }
#pragma unroll
            for (int mi = 0; mi < 2; mi++)
#pragma unroll
                for (int ni = 0; ni < 8; ni++)
                    mma16(c[mi][ni], a[mi], &bf[ni >> 1][(ni & 1) * 2]);
        }
    }

#pragma unroll
    for (int mi = 0; mi < 2; mi++) {
#pragma unroll
        for (int h = 0; h < 2; h++) {
            int r = wm * 32 + mi * 16 + g + h * 8;
            if (r < mcount) {
                float wA = wA_s[r], wB = wB_s[r];
                float* dst = out + (size_t)tok_s[r] * D_DIM + py * 256;
#pragma unroll
                for (int ni = 0; ni < 8; ni++) {
                    int col = wn * 64 + ni * 8 + tg * 2;
                    float2 v = make_float2(
                        c[mi][ni][h * 2]     + wA * b2a[col]     + wB * b2b[col],
                        c[mi][ni][h * 2 + 1] + wA * b2a[col + 1] + wB * b2b[col + 1]);
                    *(float2*)(dst + col) = v;
                }
            }
        }
    }
}

// ---------------- launch ----------------
extern "C" void kernel_launch(void* const* d_in, const int* in_sizes, int n_in,
                              void* d_out, int out_size) {
    const float* x  = (const float*)d_in[0];
    const float* gw = (const float*)d_in[1];
    const float* gb = (const float*)d_in[2];
    const float* w1 = (const float*)d_in[3];
    const float* b1 = (const float*)d_in[4];
    const float* w2 = (const float*)d_in[5];
    const float* b2 = (const float*)d_in[6];
    float* out = (float*)d_out;

    static __half* w1h_ptr = nullptr;
    static __half* w2h_ptr = nullptr;
    if (!w1h_ptr) {
        cudaGetSymbolAddress((void**)&w1h_ptr, g_w1h);
        cudaGetSymbolAddress((void**)&w2h_ptr, g_w2h);
        cudaFuncSetAttribute(gate_kernel,
                             cudaFuncAttributeMaxDynamicSharedMemorySize, GATE_DYN);
        cudaFuncSetAttribute(expert1_kernel,
                             cudaFuncAttributeMaxDynamicSharedMemorySize, DYN_SMEM);
        cudaFuncSetAttribute(expert2_kernel,
                             cudaFuncAttributeMaxDynamicSharedMemorySize, DYN_SMEM2);
    }

    prep_w_kernel<<<dim3(128, 1, 16), dim3(32, 8)>>>(w1, w2, w1h_ptr, w2h_ptr);
    gate_kernel<<<GATE_BLKS, 512, GATE_DYN>>>(x, gw, gb);
    sched_kernel<<<1, 32>>>();
    expert1_kernel<<<dim3(E1_TILES), NTHR, DYN_SMEM>>>(b1);
    expert2_kernel<<<dim3(E2_TILES, 4), 512, DYN_SMEM2>>>(b2, out);
}

// round 16
// speedup vs baseline: 1.0472x; 1.0472x over previous
#include <cuda_runtime.h>
#include <cuda_fp16.h>
#include <math.h>
#include <stdint.h>

#define B_TOK 16384
#define D_DIM 1024
#define H_DIM 256
#define E_NUM 8
#define NPAIR 28
#define TM    64
#define NTHR  256

#define E1_TILES (B_TOK * 2 / TM + E_NUM)    // 520
#define E2_TILES (B_TOK / TM + NPAIR)        // 284

// expert smem: 2-stage ring, stage = A(8KB) + B(32KB)
#define ST_SZ   40960
#define ST_B    8192
#define DYN_SMEM 81920

// gate smem: gws 32KB @0, x stages 2 x 28KB @32768
#define GATE_BLKS 293
#define GATE_TOK  56
#define GATE_STG  28672
#define GATE_DYN  (32768 + 2 * GATE_STG)

// ---------------- device scratch ----------------
__device__ int    g_cnt[E_NUM];
__device__ int    g_pc[NPAIR];
__device__ int    g_tok[E_NUM][B_TOK];
__device__ float  g_wgt[E_NUM][B_TOK];
__device__ int4   g_plist[NPAIR][B_TOK];        // {tok, slot_a, slot_b, 0}
__device__ float2 g_pwt[NPAIR][B_TOK];
__device__ __half g_xh[(size_t)B_TOK * D_DIM];
__device__ __half g_w1h[(size_t)E_NUM * H_DIM * D_DIM];
__device__ __half g_w2h[(size_t)E_NUM * D_DIM * H_DIM];
__device__ __half g_h[(size_t)E_NUM * B_TOK * H_DIM];   // wt*gelu(h) fp16

__constant__ int c_pa[NPAIR] = {0,0,0,0,0,0,0, 1,1,1,1,1,1, 2,2,2,2,2, 3,3,3,3, 4,4,4, 5,5, 6};
__constant__ int c_pb[NPAIR] = {1,2,3,4,5,6,7, 2,3,4,5,6,7, 3,4,5,6,7, 4,5,6,7, 5,6,7, 6,7, 7};

// ---------------- helpers ----------------
__device__ __forceinline__ uint32_t smem_u32(const void* p) {
    uint32_t r;
    asm("{.reg .u64 t; cvta.to.shared.u64 t,%1; cvt.u32.u64 %0,t;}" : "=r"(r) : "l"(p));
    return r;
}
__device__ __forceinline__ void cp16(uint32_t s, const void* g) {
    asm volatile("cp.async.cg.shared.global [%0],[%1],16;" :: "r"(s), "l"(g));
}
__device__ __forceinline__ void cp_commit() {
    asm volatile("cp.async.commit_group;" ::: "memory");
}
template <int N> __device__ __forceinline__ void cp_wait() {
    asm volatile("cp.async.wait_group %0;" :: "n"(N) : "memory");
}
__device__ __forceinline__ void mbar_init(uint32_t mb, uint32_t cnt) {
    asm volatile("mbarrier.init.shared.b64 [%0], %1;" :: "r"(mb), "r"(cnt) : "memory");
}
__device__ __forceinline__ void mbar_expect(uint32_t mb, uint32_t bytes) {
    asm volatile("mbarrier.arrive.expect_tx.shared.b64 _, [%0], %1;"
                 :: "r"(mb), "r"(bytes) : "memory");
}
__device__ __forceinline__ void bulk_g2s(uint32_t dst, const void* src,
                                         uint32_t bytes, uint32_t mb) {
    asm volatile(
        "cp.async.bulk.shared::cluster.global.mbarrier::complete_tx::bytes "
        "[%0], [%1], %2, [%3];"
        :: "r"(dst), "l"(src), "r"(bytes), "r"(mb) : "memory");
}
__device__ __forceinline__ void mbar_wait(uint32_t mb, uint32_t ph) {
    asm volatile(
        "{.reg .pred P;\n\t"
        "WL%=:\n\t"
        "mbarrier.try_wait.parity.acquire.cta.shared::cta.b64 P,[%0],%1,0x989680;\n\t"
        "@P bra WD%=;\n\t"
        "bra WL%=;\n\t"
        "WD%=:}" :: "r"(mb), "r"(ph) : "memory");
}
__device__ __forceinline__ void ldsm4(uint32_t* r, uint32_t a) {
    asm volatile("ldmatrix.sync.aligned.m8n8.x4.shared.b16 {%0,%1,%2,%3},[%4];"
                 : "=r"(r[0]), "=r"(r[1]), "=r"(r[2]), "=r"(r[3]) : "r"(a));
}
__device__ __forceinline__ void mma16(float* c, const uint32_t* a, const uint32_t* b) {
    asm volatile(
        "mma.sync.aligned.m16n8k16.row.col.f32.f16.f16.f32 "
        "{%0,%1,%2,%3},{%4,%5,%6,%7},{%8,%9},{%0,%1,%2,%3};"
        : "+f"(c[0]), "+f"(c[1]), "+f"(c[2]), "+f"(c[3])
        : "r"(a[0]), "r"(a[1]), "r"(a[2]), "r"(a[3]), "r"(b[0]), "r"(b[1]));
}

// ---------------- weight prep (merged): [E][K][N] fp32 -> [e][k/64][n][64] fp16 swizzled ----------------
__global__ void prep_w_kernel(const float* __restrict__ w1, const float* __restrict__ w2,
                              __half* __restrict__ d1, __half* __restrict__ d2) {
    __shared__ float tile[64][33];
    if (blockIdx.x == 0 && blockIdx.z == 0 && threadIdx.y == 0) {
        if (threadIdx.x < E_NUM) g_cnt[threadIdx.x] = 0;
        if (threadIdx.x < NPAIR) g_pc[threadIdx.x] = 0;
    }
    const int z = blockIdx.z;
    const bool is1 = z < E_NUM;
    const int e = is1 ? z : z - E_NUM;
    const int f = blockIdx.x;
    const int K = is1 ? D_DIM : H_DIM;
    const int N = is1 ? H_DIM : D_DIM;
    const int s  = is1 ? (f >> 3) : (f >> 5);
    const int n0 = (is1 ? (f & 7) : (f & 31)) * 32;
    const float* src = is1 ? w1 : w2;
    __half*      dst = is1 ? d1 : d2;

    const int tx = threadIdx.x, ty = threadIdx.y;      // 32 x 8
    const float* sp = src + (size_t)e * K * N + (size_t)s * 64 * N + n0;
#pragma unroll
    for (int dy = 0; dy < 8; dy++)
        tile[ty + dy * 8][tx] = sp[(size_t)(ty + dy * 8) * N + tx];
    __syncthreads();
    __half* dp = dst + (((size_t)e * (K / 64) + s) * N + n0) * 64;
    const int nn = n0 + tx;
#pragma unroll
    for (int dy = 0; dy < 4; dy++) {
        int k = (ty + dy * 8) * 2;
        __half2 v = __floats2half2_rn(tile[k][tx], tile[k + 1][tx]);
        *(__half2*)(dp + (size_t)tx * 64 + (((k >> 3) ^ (nn & 7)) << 3) + (k & 7)) = v;
    }
}

// ---------------- gate v3: cp.async-staged, single wave, 2 CTA/SM ----------------
__global__ __launch_bounds__(512, 2) void gate_kernel(
    const float* __restrict__ x, const float* __restrict__ gw,
    const float* __restrict__ gb)
{
    extern __shared__ __align__(16) float gsm[];       // gws @0, stages @8192 floats
    const int tid = threadIdx.x;

    for (int k = tid; k < D_DIM; k += 512) {
        float4 a = *(const float4*)(gw + k * 8);
        float4 b = *(const float4*)(gw + k * 8 + 4);
        gsm[0 * D_DIM + k] = a.x; gsm[1 * D_DIM + k] = a.y;
        gsm[2 * D_DIM + k] = a.z; gsm[3 * D_DIM + k] = a.w;
        gsm[4 * D_DIM + k] = b.x; gsm[5 * D_DIM + k] = b.y;
        gsm[6 * D_DIM + k] = b.z; gsm[7 * D_DIM + k] = b.w;
    }

    const int tok_base = blockIdx.x * GATE_TOK;
    const uint32_t stg = smem_u32(gsm) + 32768;

    auto stage = [&](int j, int buf) {
        const uint32_t db = stg + buf * GATE_STG;
#pragma unroll
        for (int t = 0; t < 4; t++) {
            int i = tid + t * 512;
            if (i < GATE_TOK * 32) {
                int r = i >> 5, u = i & 31;
                int tok = tok_base + r;
                if (tok < B_TOK)
                    cp16(db + i * 16, x + (size_t)tok * D_DIM + j * 128 + u * 4);
            }
        }
        cp_commit();
    };

    stage(0, 0);
    stage(1, 1);

    const int warp = tid >> 5, lane = tid & 31;
    const int t0 = tok_base + warp * 4;
    const int d0 = lane * 4;

    float acc[4][E_NUM];
#pragma unroll
    for (int t = 0; t < 4; t++)
#pragma unroll
        for (int e = 0; e < E_NUM; e++) acc[t][e] = 0.f;

    for (int j = 0; j < 8; j++) {
        const int buf = j & 1;
        if (j < 6) cp_wait<1>(); else cp_wait<0>();
        __syncthreads();
        if (warp < 14) {
            const float* xsb = gsm + 8192 + buf * (GATE_STG / 4);
            const int dj = j * 128 + d0;
#pragma unroll
            for (int t = 0; t < 4; t++) {
                float4 cur = *(const float4*)&xsb[(warp * 4 + t) * 128 + d0];
#pragma unroll
                for (int e = 0; e < E_NUM; e++) {
                    const float4 wv = *(const float4*)&gsm[e * D_DIM + dj];
                    acc[t][e] += cur.x * wv.x + cur.y * wv.y
                               + cur.z * wv.z + cur.w * wv.w;
                }
                if (t0 + t < B_TOK) {
                    __half2 h0 = __floats2half2_rn(cur.x, cur.y);
                    __half2 h1 = __floats2half2_rn(cur.z, cur.w);
                    uint2 u = make_uint2(*(uint32_t*)&h0, *(uint32_t*)&h1);
                    *(uint2*)(g_xh + (size_t)(t0 + t) * D_DIM + dj) = u;
                }
            }
        }
        __syncthreads();
        if (j + 2 < 8) stage(j + 2, buf);
    }

    if (warp >= 14) return;

#pragma unroll
    for (int t = 0; t < 4; t++)
#pragma unroll
        for (int e = 0; e < E_NUM; e++)
#pragma unroll
            for (int s = 16; s; s >>= 1)
                acc[t][e] += __shfl_xor_sync(0xffffffffu, acc[t][e], s);

    if (lane == 0) {
#pragma unroll
        for (int t = 0; t < 4; t++) {
            if (t0 + t >= B_TOK) break;
            float l[E_NUM];
#pragma unroll
            for (int e = 0; e < E_NUM; e++) l[e] = acc[t][e] + gb[e];
            int i0 = 0;
#pragma unroll
            for (int e = 1; e < E_NUM; e++) if (l[e] > l[i0]) i0 = e;
            int i1 = (i0 == 0) ? 1 : 0;
#pragma unroll
            for (int e = 0; e < E_NUM; e++) if (e != i0 && l[e] > l[i1]) i1 = e;
            float e1 = expf(l[i1] - l[i0]);
            float s  = 1.0f + e1;
            float wv0 = 1.0f / s, wv1 = e1 / s;
            int tok  = t0 + t;
            int p0 = atomicAdd(&g_cnt[i0], 1);
            g_tok[i0][p0] = tok; g_wgt[i0][p0] = wv0;
            int p1 = atomicAdd(&g_cnt[i1], 1);
            g_tok[i1][p1] = tok; g_wgt[i1][p1] = wv1;
            int a = min(i0, i1), b = max(i0, i1);
            int pidx = a * (2 * E_NUM - a - 1) / 2 + (b - a - 1);
            int pa = (a == i0) ? p0 : p1;
            int pb = (a == i0) ? p1 : p0;
            float wA = (a == i0) ? wv0 : wv1;
            float wB = (a == i0) ? wv1 : wv0;
            int pp = atomicAdd(&g_pc[pidx], 1);
            g_plist[pidx][pp] = make_int4(tok, pa, pb, 0);
            g_pwt[pidx][pp]   = make_float2(wA, wB);
        }
    }
}

// ---------------- E1: g_h = wt * gelu(x[64,1024] @ w1^T + b1), fp16 ----------------
__global__ void __launch_bounds__(NTHR, 2) expert1_kernel(const float* __restrict__ b1)
{
    // in-register prefix scan over 8 expert tile counts (independent LDGs)
    int tc[E_NUM];
#pragma unroll
    for (int k = 0; k < E_NUM; k++) tc[k] = (__ldg(&g_cnt[k]) + TM - 1) / TM;
    int e = -1, start = 0, pre = 0;
#pragma unroll
    for (int k = 0; k < E_NUM; k++) {
        if (e < 0 && blockIdx.x < pre + tc[k]) { e = k; start = (blockIdx.x - pre) * TM; }
        pre += tc[k];
    }
    if (e < 0) return;
    const int cnt = g_cnt[e];

    __shared__ int   tids_s[TM];
    __shared__ float wts_s[TM];
    __shared__ __align__(8) uint64_t mbar_s[2];
    extern __shared__ __align__(16) char smem[];
    const uint32_t sb = smem_u32(smem);

    const int tid = threadIdx.x;
    if (tid < TM) {
        bool v = tid < cnt - start;
        int  src = v ? (start + tid) : start;
        tids_s[tid] = g_tok[e][src];
        wts_s[tid]  = v ? g_wgt[e][src] : 0.f;
    }
    const uint32_t mb[2] = { smem_u32(&mbar_s[0]), smem_u32(&mbar_s[1]) };
    if (tid == 0) { mbar_init(mb[0], 1); mbar_init(mb[1], 1); }
    __syncthreads();

    const int warp = tid >> 5, lane = tid & 31;
    const int wm = warp & 1, wn = warp >> 1;
    const int sub = lane >> 3, rin = lane & 7;
    const int g = lane >> 2, tg = lane & 3;
    const int arl = (sub & 1) * 8 + rin, auo = sub >> 1;
    const int brl = ((sub >> 1) & 1) * 8 + rin, buo = sub & 1;

    const __half* w1h = g_w1h + (size_t)e * 16 * 16384;
    const float*  b1e = b1 + e * H_DIM;

    const int r0 = tid >> 2, u0 = tid & 3, u1 = u0 + 4;
    const __half* ga0 = g_xh + (size_t)tids_s[r0] * D_DIM + u0 * 8;
    const __half* ga1 = g_xh + (size_t)tids_s[r0] * D_DIM + u1 * 8;
    const uint32_t sa0 = r0 * 128 + ((u0 ^ (r0 & 7)) << 4);
    const uint32_t sa1 = r0 * 128 + ((u1 ^ (r0 & 7)) << 4);

    float c[2][8][4];
#pragma unroll
    for (int mi = 0; mi < 2; mi++)
#pragma unroll
        for (int ni = 0; ni < 8; ni++)
#pragma unroll
            for (int q = 0; q < 4; q++) c[mi][ni][q] = 0.f;

    int ph[2] = {0, 0};

    if (tid == 0) { mbar_expect(mb[0], 32768); bulk_g2s(sb + ST_B, w1h, 32768, mb[0]); }
    cp16(sb + sa0, ga0); cp16(sb + sa1, ga1); cp_commit();

    for (int i = 0; i < 16; i++) {
        const int b = i & 1;
        cp_wait<0>();
        mbar_wait(mb[b], ph[b]); ph[b] ^= 1;
        __syncthreads();
        if (i + 1 < 16) {
            const int nb = b ^ 1;
            const uint32_t st = sb + nb * ST_SZ;
            if (tid == 0) {
                mbar_expect(mb[nb], 32768);
                bulk_g2s(st + ST_B, w1h + (size_t)(i + 1) * 16384, 32768, mb[nb]);
            }
            cp16(st + sa0, ga0 + (i + 1) * 64);
            cp16(st + sa1, ga1 + (i + 1) * 64);
            cp_commit();
        }
        const uint32_t Ab = sb + b * ST_SZ;
        const uint32_t Bb = Ab + ST_B;
#pragma unroll
        for (int kk = 0; kk < 4; kk++) {
            uint32_t a[2][4], bf[4][4];
#pragma unroll
            for (int mi = 0; mi < 2; mi++) {
                int row = wm * 32 + mi * 16 + arl;
                int u   = 2 * kk + auo;
                ldsm4(a[mi], Ab + row * 128 + ((u ^ (row & 7)) << 4));
            }
#pragma unroll
            for (int p = 0; p < 4; p++) {
                int row = wn * 64 + p * 16 + brl;
                int u   = 2 * kk + buo;
                ldsm4(bf[p], Bb + row * 128 + ((u ^ (row & 7)) << 4));
            }
#pragma unroll
            for (int mi = 0; mi < 2; mi++)
#pragma unroll
                for (int ni = 0; ni < 8; ni++)
                    mma16(c[mi][ni], a[mi], &bf[ni >> 1][(ni & 1) * 2]);
        }
    }
    __syncthreads();   // ring dead; reuse as staging [64][272] halves

#pragma unroll
    for (int mi = 0; mi < 2; mi++) {
#pragma unroll
        for (int ni = 0; ni < 8; ni++) {
            int col = wn * 64 + ni * 8 + tg * 2;
            float bb0 = b1e[col], bb1 = b1e[col + 1];
#pragma unroll
            for (int h = 0; h < 2; h++) {
                int row = wm * 32 + mi * 16 + g + h * 8;
                float wt = wts_s[row];
                float v0 = c[mi][ni][h * 2]     + bb0;
                float v1 = c[mi][ni][h * 2 + 1] + bb1;
                v0 = wt * (0.5f * v0 * (1.0f + erff(v0 * 0.70710678f)));
                v1 = wt * (0.5f * v1 * (1.0f + erff(v1 * 0.70710678f)));
                __half2 hv = __floats2half2_rn(v0, v1);
                asm volatile("st.shared.b32 [%0],%1;"
                             :: "r"(sb + (row * 272 + col) * 2), "r"(*(uint32_t*)&hv));
            }
        }
    }
    __syncthreads();

    __half* hdst = g_h + ((size_t)e * B_TOK + start) * H_DIM;
#pragma unroll
    for (int t = 0; t < 8; t++) {
        int ch = tid + t * NTHR;
        int row = ch >> 5, c4 = ch & 31;
        uint4 v;
        asm volatile("ld.shared.v4.b32 {%0,%1,%2,%3},[%4];"
                     : "=r"(v.x), "=r"(v.y), "=r"(v.z), "=r"(v.w)
                     : "r"(sb + row * 544 + c4 * 16));
        *(uint4*)(hdst + (size_t)row * H_DIM + c4 * 8) = v;
    }
}

// ---------------- E2: pair-bucketed K=512 GEMM, flat-tiled, plain stores ----------------
__global__ void __launch_bounds__(NTHR, 2) expert2_kernel(
    const float* __restrict__ b2, float* __restrict__ out)
{
    // in-register prefix scan over 28 pair tile counts (independent LDGs)
    int tc[NPAIR];
#pragma unroll
    for (int k = 0; k < NPAIR; k++) tc[k] = (__ldg(&g_pc[k]) + TM - 1) / TM;
    int p = -1, start = 0, pre = 0;
#pragma unroll
    for (int k = 0; k < NPAIR; k++) {
        if (p < 0 && blockIdx.x < pre + tc[k]) { p = k; start = (blockIdx.x - pre) * TM; }
        pre += tc[k];
    }
    if (p < 0) return;
    const int py    = blockIdx.y;
    const int cnt   = g_pc[p];
    const int mcount = min(TM, cnt - start);
    const int ea = c_pa[p], eb = c_pb[p];

    __shared__ int   tok_s[TM];
    __shared__ int   pa_s[TM], pb_s[TM];
    __shared__ float wA_s[TM], wB_s[TM];
    __shared__ __align__(8) uint64_t mbar_s[2];
    extern __shared__ __align__(16) char smem[];
    const uint32_t sb = smem_u32(smem);

    const int tid = threadIdx.x;
    if (tid < TM) {
        bool v = tid < mcount;
        int  q = v ? (start + tid) : start;
        int4 pl = g_plist[p][q];
        float2 pw = g_pwt[p][q];
        tok_s[tid] = pl.x;
        pa_s[tid]  = pl.y;
        pb_s[tid]  = pl.z;
        wA_s[tid]  = v ? pw.x : 0.f;
        wB_s[tid]  = v ? pw.y : 0.f;
    }
    const uint32_t mb[2] = { smem_u32(&mbar_s[0]), smem_u32(&mbar_s[1]) };
    if (tid == 0) { mbar_init(mb[0], 1); mbar_init(mb[1], 1); }
    __syncthreads();

    const int warp = tid >> 5, lane = tid & 31;
    const int wm = warp & 1, wn = warp >> 1;
    const int sub = lane >> 3, rin = lane & 7;
    const int g = lane >> 2, tg = lane & 3;
    const int arl = (sub & 1) * 8 + rin, auo = sub >> 1;
    const int brl = ((sub >> 1) & 1) * 8 + rin, buo = sub & 1;

    const __half* w2a = g_w2h + (size_t)ea * 4 * 65536 + (size_t)py * 256 * 64;
    const __half* w2b = g_w2h + (size_t)eb * 4 * 65536 + (size_t)py * 256 * 64;
    const float*  b2a = b2 + ea * D_DIM + py * 256;
    const float*  b2b = b2 + eb * D_DIM + py * 256;

    const int r0 = tid >> 2, u0 = tid & 3, u1 = u0 + 4;
    const __half* hA0 = g_h + ((size_t)ea * B_TOK + pa_s[r0]) * H_DIM + u0 * 8;
    const __half* hA1 = g_h + ((size_t)ea * B_TOK + pa_s[r0]) * H_DIM + u1 * 8;
    const __half* hB0 = g_h + ((size_t)eb * B_TOK + pb_s[r0]) * H_DIM + u0 * 8;
    const __half* hB1 = g_h + ((size_t)eb * B_TOK + pb_s[r0]) * H_DIM + u1 * 8;
    const uint32_t sa0 = r0 * 128 + ((u0 ^ (r0 & 7)) << 4);
    const uint32_t sa1 = r0 * 128 + ((u1 ^ (r0 & 7)) << 4);

    float c[2][8][4];
#pragma unroll
    for (int mi = 0; mi < 2; mi++)
#pragma unroll
        for (int ni = 0; ni < 8; ni++)
#pragma unroll
            for (int q = 0; q < 4; q++) c[mi][ni][q] = 0.f;

    int ph[2] = {0, 0};

    if (tid == 0) { mbar_expect(mb[0], 32768); bulk_g2s(sb + ST_B, w2a, 32768, mb[0]); }
    cp16(sb + sa0, hA0); cp16(sb + sa1, hA1); cp_commit();

    for (int i = 0; i < 8; i++) {
        const int b = i & 1;
        cp_wait<0>();
        mbar_wait(mb[b], ph[b]); ph[b] ^= 1;
        __syncthreads();
        if (i + 1 < 8) {
            const int nsl = i + 1, nb = b ^ 1;
            const uint32_t st = sb + nb * ST_SZ;
            const __half* ws = (nsl < 4) ? (w2a + (size_t)nsl * 65536)
                                         : (w2b + (size_t)(nsl - 4) * 65536);
            if (tid == 0) { mbar_expect(mb[nb], 32768); bulk_g2s(st + ST_B, ws, 32768, mb[nb]); }
            const __half* s0 = (nsl < 4) ? (hA0 + nsl * 64) : (hB0 + (nsl - 4) * 64);
            const __half* s1 = (nsl < 4) ? (hA1 + nsl * 64) : (hB1 + (nsl - 4) * 64);
            cp16(st + sa0, s0);
            cp16(st + sa1, s1);
            cp_commit();
        }
        const uint32_t Ab = sb + b * ST_SZ;
        const uint32_t Bb = Ab + ST_B;
#pragma unroll
        for (int kk = 0; kk < 4; kk++) {
            uint32_t a[2][4], bf[4][4];
#pragma unroll
            for (int mi = 0; mi < 2; mi++) {
                int row = wm * 32 + mi * 16 + arl;
                int u   = 2 * kk + auo;
                ldsm4(a[mi], Ab + row * 128 + ((u ^ (row & 7)) << 4));
            }
#pragma unroll
            for (int q = 0; q < 4; q++) {
                int row = wn * 64 + q * 16 + brl;
                int u   = 2 * kk + buo;
                ldsm4(bf[q], Bb + row * 128 + ((u ^ (row & 7)) << 4));
            }
#pragma unroll
            for (int mi = 0; mi < 2; mi++)
#pragma unroll
                for (int ni = 0; ni < 8; ni++)
                    mma16(c[mi][ni], a[mi], &bf[ni >> 1][(ni & 1) * 2]);
        }
    }

#pragma unroll
    for (int mi = 0; mi < 2; mi++) {
#pragma unroll
        for (int h = 0; h < 2; h++) {
            int r = wm * 32 + mi * 16 + g + h * 8;
            if (r < mcount) {
                float wA = wA_s[r], wB = wB_s[r];
                float* dst = out + (size_t)tok_s[r] * D_DIM + py * 256;
#pragma unroll
                for (int ni = 0; ni < 8; ni++) {
                    int col = wn * 64 + ni * 8 + tg * 2;
                    float2 v = make_float2(
                        c[mi][ni][h * 2]     + wA * b2a[col]     + wB * b2b[col],
                        c[mi][ni][h * 2 + 1] + wA * b2a[col + 1] + wB * b2b[col + 1]);
                    *(float2*)(dst + col) = v;
                }
            }
        }
    }
}

// ---------------- launch ----------------
extern "C" void kernel_launch(void* const* d_in, const int* in_sizes, int n_in,
                              void* d_out, int out_size) {
    const float* x  = (const float*)d_in[0];
    const float* gw = (const float*)d_in[1];
    const float* gb = (const float*)d_in[2];
    const float* w1 = (const float*)d_in[3];
    const float* b1 = (const float*)d_in[4];
    const float* w2 = (const float*)d_in[5];
    const float* b2 = (const float*)d_in[6];
    float* out = (float*)d_out;

    static __half* w1h_ptr = nullptr;
    static __half* w2h_ptr = nullptr;
    if (!w1h_ptr) {
        cudaGetSymbolAddress((void**)&w1h_ptr, g_w1h);
        cudaGetSymbolAddress((void**)&w2h_ptr, g_w2h);
        cudaFuncSetAttribute(gate_kernel,
                             cudaFuncAttributeMaxDynamicSharedMemorySize, GATE_DYN);
        cudaFuncSetAttribute(expert1_kernel,
                             cudaFuncAttributeMaxDynamicSharedMemorySize, DYN_SMEM);
        cudaFuncSetAttribute(expert2_kernel,
                             cudaFuncAttributeMaxDynamicSharedMemorySize, DYN_SMEM);
    }

    prep_w_kernel<<<dim3(128, 1, 16), dim3(32, 8)>>>(w1, w2, w1h_ptr, w2h_ptr);
    gate_kernel<<<GATE_BLKS, 512, GATE_DYN>>>(x, gw, gb);
    expert1_kernel<<<dim3(E1_TILES), NTHR, DYN_SMEM>>>(b1);
    expert2_kernel<<<dim3(E2_TILES, 4), NTHR, DYN_SMEM>>>(b2, out);
}

// round 17
// speedup vs baseline: 1.1415x; 1.0900x over previous
#include <cuda_runtime.h>
#include <cuda_fp16.h>
#include <math.h>
#include <stdint.h>

#define B_TOK 16384
#define D_DIM 1024
#define H_DIM 256
#define E_NUM 8
#define NPAIR 28
#define TM    64
#define NTHR  256

#define E1_TILES (B_TOK * 2 / TM + E_NUM)    // 520
#define E2_TILES (B_TOK / TM + NPAIR)        // 284

// expert smem: 2-stage ring, stage = A(8KB) + B(32KB)
#define ST_SZ   40960
#define ST_B    8192
#define DYN_SMEM 81920

// gate smem: gws 32KB @0, x stages 2 x 28KB @32768
#define GATE_BLKS 293
#define GATE_TOK  56
#define GATE_STG  28672
#define GATE_DYN  (32768 + 2 * GATE_STG)

// ---------------- device scratch ----------------
__device__ int    g_cnt[E_NUM];
__device__ int    g_pc[NPAIR];
__device__ int    g_tok[E_NUM][B_TOK];
__device__ float  g_wgt[E_NUM][B_TOK];
__device__ int4   g_plist[NPAIR][B_TOK];        // {tok, slot_a, slot_b, 0}
__device__ float2 g_pwt[NPAIR][B_TOK];
__device__ __half g_xh[(size_t)B_TOK * D_DIM];
__device__ __half g_w1h[(size_t)E_NUM * H_DIM * D_DIM];
__device__ __half g_w2h[(size_t)E_NUM * D_DIM * H_DIM];
__device__ __half g_h[(size_t)E_NUM * B_TOK * H_DIM];   // wt*gelu(h) fp16

__constant__ int c_pa[NPAIR] = {0,0,0,0,0,0,0, 1,1,1,1,1,1, 2,2,2,2,2, 3,3,3,3, 4,4,4, 5,5, 6};
__constant__ int c_pb[NPAIR] = {1,2,3,4,5,6,7, 2,3,4,5,6,7, 3,4,5,6,7, 4,5,6,7, 5,6,7, 6,7, 7};

// ---------------- helpers ----------------
__device__ __forceinline__ uint32_t smem_u32(const void* p) {
    uint32_t r;
    asm("{.reg .u64 t; cvta.to.shared.u64 t,%1; cvt.u32.u64 %0,t;}" : "=r"(r) : "l"(p));
    return r;
}
__device__ __forceinline__ void cp16(uint32_t s, const void* g) {
    asm volatile("cp.async.cg.shared.global [%0],[%1],16;" :: "r"(s), "l"(g));
}
__device__ __forceinline__ void cp_commit() {
    asm volatile("cp.async.commit_group;" ::: "memory");
}
template <int N> __device__ __forceinline__ void cp_wait() {
    asm volatile("cp.async.wait_group %0;" :: "n"(N) : "memory");
}
__device__ __forceinline__ void mbar_init(uint32_t mb, uint32_t cnt) {
    asm volatile("mbarrier.init.shared.b64 [%0], %1;" :: "r"(mb), "r"(cnt) : "memory");
}
__device__ __forceinline__ void mbar_expect(uint32_t mb, uint32_t bytes) {
    asm volatile("mbarrier.arrive.expect_tx.shared.b64 _, [%0], %1;"
                 :: "r"(mb), "r"(bytes) : "memory");
}
__device__ __forceinline__ void bulk_g2s(uint32_t dst, const void* src,
                                         uint32_t bytes, uint32_t mb) {
    asm volatile(
        "cp.async.bulk.shared::cluster.global.mbarrier::complete_tx::bytes "
        "[%0], [%1], %2, [%3];"
        :: "r"(dst), "l"(src), "r"(bytes), "r"(mb) : "memory");
}
__device__ __forceinline__ void mbar_wait(uint32_t mb, uint32_t ph) {
    asm volatile(
        "{.reg .pred P;\n\t"
        "WL%=:\n\t"
        "mbarrier.try_wait.parity.acquire.cta.shared::cta.b64 P,[%0],%1,0x989680;\n\t"
        "@P bra WD%=;\n\t"
        "bra WL%=;\n\t"
        "WD%=:}" :: "r"(mb), "r"(ph) : "memory");
}
__device__ __forceinline__ void ldsm4(uint32_t* r, uint32_t a) {
    asm volatile("ldmatrix.sync.aligned.m8n8.x4.shared.b16 {%0,%1,%2,%3},[%4];"
                 : "=r"(r[0]), "=r"(r[1]), "=r"(r[2]), "=r"(r[3]) : "r"(a));
}
__device__ __forceinline__ void mma16(float* c, const uint32_t* a, const uint32_t* b) {
    asm volatile(
        "mma.sync.aligned.m16n8k16.row.col.f32.f16.f16.f32 "
        "{%0,%1,%2,%3},{%4,%5,%6,%7},{%8,%9},{%0,%1,%2,%3};"
        : "+f"(c[0]), "+f"(c[1]), "+f"(c[2]), "+f"(c[3])
        : "r"(a[0]), "r"(a[1]), "r"(a[2]), "r"(a[3]), "r"(b[0]), "r"(b[1]));
}

// ---------------- weight prep (merged): [E][K][N] fp32 -> [e][k/64][n][64] fp16 swizzled ----------------
__global__ void prep_w_kernel(const float* __restrict__ w1, const float* __restrict__ w2,
                              __half* __restrict__ d1, __half* __restrict__ d2) {
    __shared__ float tile[64][33];
    if (blockIdx.x == 0 && blockIdx.z == 0 && threadIdx.y == 0) {
        if (threadIdx.x < E_NUM) g_cnt[threadIdx.x] = 0;
        if (threadIdx.x < NPAIR) g_pc[threadIdx.x] = 0;
    }
    const int z = blockIdx.z;
    const bool is1 = z < E_NUM;
    const int e = is1 ? z : z - E_NUM;
    const int f = blockIdx.x;
    const int K = is1 ? D_DIM : H_DIM;
    const int N = is1 ? H_DIM : D_DIM;
    const int s  = is1 ? (f >> 3) : (f >> 5);
    const int n0 = (is1 ? (f & 7) : (f & 31)) * 32;
    const float* src = is1 ? w1 : w2;
    __half*      dst = is1 ? d1 : d2;

    const int tx = threadIdx.x, ty = threadIdx.y;      // 32 x 8
    const float* sp = src + (size_t)e * K * N + (size_t)s * 64 * N + n0;
#pragma unroll
    for (int dy = 0; dy < 8; dy++)
        tile[ty + dy * 8][tx] = sp[(size_t)(ty + dy * 8) * N + tx];
    __syncthreads();
    __half* dp = dst + (((size_t)e * (K / 64) + s) * N + n0) * 64;
    const int nn = n0 + tx;
#pragma unroll
    for (int dy = 0; dy < 4; dy++) {
        int k = (ty + dy * 8) * 2;
        __half2 v = __floats2half2_rn(tile[k][tx], tile[k + 1][tx]);
        *(__half2*)(dp + (size_t)tx * 64 + (((k >> 3) ^ (nn & 7)) << 3) + (k & 7)) = v;
    }
}

// ---------------- gate v4: staged x, block-aggregated scatter atomics ----------------
__global__ __launch_bounds__(512) void gate_kernel(
    const float* __restrict__ x, const float* __restrict__ gw,
    const float* __restrict__ gb)
{
    extern __shared__ __align__(16) float gsm[];       // gws @0, stages @8192 floats
    __shared__ int   lc[E_NUM], lpc[NPAIR];
    __shared__ int   sbase_e[E_NUM], sbase_p[NPAIR];
    __shared__ short s_i0[GATE_TOK], s_i1[GATE_TOK], s_px[GATE_TOK];
    __shared__ float s_w0[GATE_TOK], s_w1[GATE_TOK];
    __shared__ int   s_l0[GATE_TOK], s_l1[GATE_TOK], s_lp[GATE_TOK];

    const int tid = threadIdx.x;
    if (tid < E_NUM) lc[tid] = 0;
    if (tid >= 32 && tid < 32 + NPAIR) lpc[tid - 32] = 0;

    for (int k = tid; k < D_DIM; k += 512) {
        float4 a = *(const float4*)(gw + k * 8);
        float4 b = *(const float4*)(gw + k * 8 + 4);
        gsm[0 * D_DIM + k] = a.x; gsm[1 * D_DIM + k] = a.y;
        gsm[2 * D_DIM + k] = a.z; gsm[3 * D_DIM + k] = a.w;
        gsm[4 * D_DIM + k] = b.x; gsm[5 * D_DIM + k] = b.y;
        gsm[6 * D_DIM + k] = b.z; gsm[7 * D_DIM + k] = b.w;
    }

    const int tok_base = blockIdx.x * GATE_TOK;
    const uint32_t stg = smem_u32(gsm) + 32768;

    auto stage = [&](int j, int buf) {
        const uint32_t db = stg + buf * GATE_STG;
#pragma unroll
        for (int t = 0; t < 4; t++) {
            int i = tid + t * 512;
            if (i < GATE_TOK * 32) {
                int r = i >> 5, u = i & 31;
                int tok = tok_base + r;
                if (tok < B_TOK)
                    cp16(db + i * 16, x + (size_t)tok * D_DIM + j * 128 + u * 4);
            }
        }
        cp_commit();
    };

    stage(0, 0);
    stage(1, 1);

    const int warp = tid >> 5, lane = tid & 31;
    const int t0 = tok_base + warp * 4;
    const int d0 = lane * 4;

    float acc[4][E_NUM];
#pragma unroll
    for (int t = 0; t < 4; t++)
#pragma unroll
        for (int e = 0; e < E_NUM; e++) acc[t][e] = 0.f;

    for (int j = 0; j < 8; j++) {
        const int buf = j & 1;
        if (j < 6) cp_wait<1>(); else cp_wait<0>();
        __syncthreads();
        if (warp < 14) {
            const float* xsb = gsm + 8192 + buf * (GATE_STG / 4);
            const int dj = j * 128 + d0;
#pragma unroll
            for (int t = 0; t < 4; t++) {
                float4 cur = *(const float4*)&xsb[(warp * 4 + t) * 128 + d0];
#pragma unroll
                for (int e = 0; e < E_NUM; e++) {
                    const float4 wv = *(const float4*)&gsm[e * D_DIM + dj];
                    acc[t][e] += cur.x * wv.x + cur.y * wv.y
                               + cur.z * wv.z + cur.w * wv.w;
                }
                if (t0 + t < B_TOK) {
                    __half2 h0 = __floats2half2_rn(cur.x, cur.y);
                    __half2 h1 = __floats2half2_rn(cur.z, cur.w);
                    uint2 u = make_uint2(*(uint32_t*)&h0, *(uint32_t*)&h1);
                    *(uint2*)(g_xh + (size_t)(t0 + t) * D_DIM + dj) = u;
                }
            }
        }
        __syncthreads();
        if (j + 2 < 8) stage(j + 2, buf);
    }

    // ---- phase 1: top-2 + LOCAL slot claims (shared atomics) ----
    if (warp < 14) {
#pragma unroll
        for (int t = 0; t < 4; t++)
#pragma unroll
            for (int e = 0; e < E_NUM; e++)
#pragma unroll
                for (int s = 16; s; s >>= 1)
                    acc[t][e] += __shfl_xor_sync(0xffffffffu, acc[t][e], s);

        if (lane == 0) {
#pragma unroll
            for (int t = 0; t < 4; t++) {
                if (t0 + t < B_TOK) {
                    float l[E_NUM];
#pragma unroll
                    for (int e = 0; e < E_NUM; e++) l[e] = acc[t][e] + gb[e];
                    int i0 = 0;
#pragma unroll
                    for (int e = 1; e < E_NUM; e++) if (l[e] > l[i0]) i0 = e;
                    int i1 = (i0 == 0) ? 1 : 0;
#pragma unroll
                    for (int e = 0; e < E_NUM; e++) if (e != i0 && l[e] > l[i1]) i1 = e;
                    float e1 = expf(l[i1] - l[i0]);
                    float s  = 1.0f + e1;
                    int lt = warp * 4 + t;
                    s_i0[lt] = (short)i0; s_i1[lt] = (short)i1;
                    s_w0[lt] = 1.0f / s;  s_w1[lt] = e1 / s;
                    s_l0[lt] = atomicAdd(&lc[i0], 1);
                    s_l1[lt] = atomicAdd(&lc[i1], 1);
                    int a = min(i0, i1), b = max(i0, i1);
                    int pidx = a * (2 * E_NUM - a - 1) / 2 + (b - a - 1);
                    s_px[lt] = (short)pidx;
                    s_lp[lt] = atomicAdd(&lpc[pidx], 1);
                }
            }
        }
    }
    __syncthreads();

    // ---- phase 2: one global atomic per (block, expert/pair) ----
    if (tid < E_NUM)                  sbase_e[tid]      = atomicAdd(&g_cnt[tid], lc[tid]);
    if (tid >= 32 && tid < 32 + NPAIR) sbase_p[tid - 32] = atomicAdd(&g_pc[tid - 32], lpc[tid - 32]);
    __syncthreads();

    // ---- phase 3: write scatter entries with base+local slots ----
    if (tid < GATE_TOK) {
        int tok = tok_base + tid;
        if (tok < B_TOK) {
            int i0 = s_i0[tid], i1 = s_i1[tid];
            float w0 = s_w0[tid], w1 = s_w1[tid];
            int p0 = sbase_e[i0] + s_l0[tid];
            int p1 = sbase_e[i1] + s_l1[tid];
            g_tok[i0][p0] = tok; g_wgt[i0][p0] = w0;
            g_tok[i1][p1] = tok; g_wgt[i1][p1] = w1;
            int pidx = s_px[tid];
            int pp = sbase_p[pidx] + s_lp[tid];
            bool aIs0 = (c_pa[pidx] == i0);
            g_plist[pidx][pp] = make_int4(tok, aIs0 ? p0 : p1, aIs0 ? p1 : p0, 0);
            g_pwt[pidx][pp]   = make_float2(aIs0 ? w0 : w1, aIs0 ? w1 : w0);
        }
    }
}

// ---------------- E1: g_h = wt * gelu(x[64,1024] @ w1^T + b1), fp16 ----------------
__global__ void __launch_bounds__(NTHR, 2) expert1_kernel(const float* __restrict__ b1)
{
    int tc[E_NUM];
#pragma unroll
    for (int k = 0; k < E_NUM; k++) tc[k] = (__ldg(&g_cnt[k]) + TM - 1) / TM;
    int e = -1, start = 0, pre = 0;
#pragma unroll
    for (int k = 0; k < E_NUM; k++) {
        if (e < 0 && blockIdx.x < pre + tc[k]) { e = k; start = (blockIdx.x - pre) * TM; }
        pre += tc[k];
    }
    if (e < 0) return;
    const int cnt = g_cnt[e];

    __shared__ int   tids_s[TM];
    __shared__ float wts_s[TM];
    __shared__ __align__(8) uint64_t mbar_s[2];
    extern __shared__ __align__(16) char smem[];
    const uint32_t sb = smem_u32(smem);

    const int tid = threadIdx.x;
    if (tid < TM) {
        bool v = tid < cnt - start;
        int  src = v ? (start + tid) : start;
        tids_s[tid] = g_tok[e][src];
        wts_s[tid]  = v ? g_wgt[e][src] : 0.f;
    }
    const uint32_t mb[2] = { smem_u32(&mbar_s[0]), smem_u32(&mbar_s[1]) };
    if (tid == 0) { mbar_init(mb[0], 1); mbar_init(mb[1], 1); }
    __syncthreads();

    const int warp = tid >> 5, lane = tid & 31;
    const int wm = warp & 1, wn = warp >> 1;
    const int sub = lane >> 3, rin = lane & 7;
    const int g = lane >> 2, tg = lane & 3;
    const int arl = (sub & 1) * 8 + rin, auo = sub >> 1;
    const int brl = ((sub >> 1) & 1) * 8 + rin, buo = sub & 1;

    const __half* w1h = g_w1h + (size_t)e * 16 * 16384;
    const float*  b1e = b1 + e * H_DIM;

    const int r0 = tid >> 2, u0 = tid & 3, u1 = u0 + 4;
    const __half* ga0 = g_xh + (size_t)tids_s[r0] * D_DIM + u0 * 8;
    const __half* ga1 = g_xh + (size_t)tids_s[r0] * D_DIM + u1 * 8;
    const uint32_t sa0 = r0 * 128 + ((u0 ^ (r0 & 7)) << 4);
    const uint32_t sa1 = r0 * 128 + ((u1 ^ (r0 & 7)) << 4);

    float c[2][8][4];
#pragma unroll
    for (int mi = 0; mi < 2; mi++)
#pragma unroll
        for (int ni = 0; ni < 8; ni++)
#pragma unroll
            for (int q = 0; q < 4; q++) c[mi][ni][q] = 0.f;

    int ph[2] = {0, 0};

    if (tid == 0) { mbar_expect(mb[0], 32768); bulk_g2s(sb + ST_B, w1h, 32768, mb[0]); }
    cp16(sb + sa0, ga0); cp16(sb + sa1, ga1); cp_commit();

    for (int i = 0; i < 16; i++) {
        const int b = i & 1;
        cp_wait<0>();
        mbar_wait(mb[b], ph[b]); ph[b] ^= 1;
        __syncthreads();
        if (i + 1 < 16) {
            const int nb = b ^ 1;
            const uint32_t st = sb + nb * ST_SZ;
            if (tid == 0) {
                mbar_expect(mb[nb], 32768);
                bulk_g2s(st + ST_B, w1h + (size_t)(i + 1) * 16384, 32768, mb[nb]);
            }
            cp16(st + sa0, ga0 + (i + 1) * 64);
            cp16(st + sa1, ga1 + (i + 1) * 64);
            cp_commit();
        }
        const uint32_t Ab = sb + b * ST_SZ;
        const uint32_t Bb = Ab + ST_B;
#pragma unroll
        for (int kk = 0; kk < 4; kk++) {
            uint32_t a[2][4], bf[4][4];
#pragma unroll
            for (int mi = 0; mi < 2; mi++) {
                int row = wm * 32 + mi * 16 + arl;
                int u   = 2 * kk + auo;
                ldsm4(a[mi], Ab + row * 128 + ((u ^ (row & 7)) << 4));
            }
#pragma unroll
            for (int p = 0; p < 4; p++) {
                int row = wn * 64 + p * 16 + brl;
                int u   = 2 * kk + buo;
                ldsm4(bf[p], Bb + row * 128 + ((u ^ (row & 7)) << 4));
            }
#pragma unroll
            for (int mi = 0; mi < 2; mi++)
#pragma unroll
                for (int ni = 0; ni < 8; ni++)
                    mma16(c[mi][ni], a[mi], &bf[ni >> 1][(ni & 1) * 2]);
        }
    }
    __syncthreads();   // ring dead; reuse as staging [64][272] halves

#pragma unroll
    for (int mi = 0; mi < 2; mi++) {
#pragma unroll
        for (int ni = 0; ni < 8; ni++) {
            int col = wn * 64 + ni * 8 + tg * 2;
            float bb0 = b1e[col], bb1 = b1e[col + 1];
#pragma unroll
            for (int h = 0; h < 2; h++) {
                int row = wm * 32 + mi * 16 + g + h * 8;
                float wt = wts_s[row];
                float v0 = c[mi][ni][h * 2]     + bb0;
                float v1 = c[mi][ni][h * 2 + 1] + bb1;
                v0 = wt * (0.5f * v0 * (1.0f + erff(v0 * 0.70710678f)));
                v1 = wt * (0.5f * v1 * (1.0f + erff(v1 * 0.70710678f)));
                __half2 hv = __floats2half2_rn(v0, v1);
                asm volatile("st.shared.b32 [%0],%1;"
                             :: "r"(sb + (row * 272 + col) * 2), "r"(*(uint32_t*)&hv));
            }
        }
    }
    __syncthreads();

    __half* hdst = g_h + ((size_t)e * B_TOK + start) * H_DIM;
#pragma unroll
    for (int t = 0; t < 8; t++) {
        int ch = tid + t * NTHR;
        int row = ch >> 5, c4 = ch & 31;
        uint4 v;
        asm volatile("ld.shared.v4.b32 {%0,%1,%2,%3},[%4];"
                     : "=r"(v.x), "=r"(v.y), "=r"(v.z), "=r"(v.w)
                     : "r"(sb + row * 544 + c4 * 16));
        *(uint4*)(hdst + (size_t)row * H_DIM + c4 * 8) = v;
    }
}

// ---------------- E2: pair-bucketed K=512 GEMM, flat-tiled, plain stores ----------------
__global__ void __launch_bounds__(NTHR, 2) expert2_kernel(
    const float* __restrict__ b2, float* __restrict__ out)
{
    int tc[NPAIR];
#pragma unroll
    for (int k = 0; k < NPAIR; k++) tc[k] = (__ldg(&g_pc[k]) + TM - 1) / TM;
    int p = -1, start = 0, pre = 0;
#pragma unroll
    for (int k = 0; k < NPAIR; k++) {
        if (p < 0 && blockIdx.x < pre + tc[k]) { p = k; start = (blockIdx.x - pre) * TM; }
        pre += tc[k];
    }
    if (p < 0) return;
    const int py    = blockIdx.y;
    const int cnt   = g_pc[p];
    const int mcount = min(TM, cnt - start);
    const int ea = c_pa[p], eb = c_pb[p];

    __shared__ int   tok_s[TM];
    __shared__ int   pa_s[TM], pb_s[TM];
    __shared__ float wA_s[TM], wB_s[TM];
    __shared__ __align__(8) uint64_t mbar_s[2];
    extern __shared__ __align__(16) char smem[];
    const uint32_t sb = smem_u32(smem);

    const int tid = threadIdx.x;
    if (tid < TM) {
        bool v = tid < mcount;
        int  q = v ? (start + tid) : start;
        int4 pl = g_plist[p][q];
        float2 pw = g_pwt[p][q];
        tok_s[tid] = pl.x;
        pa_s[tid]  = pl.y;
        pb_s[tid]  = pl.z;
        wA_s[tid]  = v ? pw.x : 0.f;
        wB_s[tid]  = v ? pw.y : 0.f;
    }
    const uint32_t mb[2] = { smem_u32(&mbar_s[0]), smem_u32(&mbar_s[1]) };
    if (tid == 0) { mbar_init(mb[0], 1); mbar_init(mb[1], 1); }
    __syncthreads();

    const int warp = tid >> 5, lane = tid & 31;
    const int wm = warp & 1, wn = warp >> 1;
    const int sub = lane >> 3, rin = lane & 7;
    const int g = lane >> 2, tg = lane & 3;
    const int arl = (sub & 1) * 8 + rin, auo = sub >> 1;
    const int brl = ((sub >> 1) & 1) * 8 + rin, buo = sub & 1;

    const __half* w2a = g_w2h + (size_t)ea * 4 * 65536 + (size_t)py * 256 * 64;
    const __half* w2b = g_w2h + (size_t)eb * 4 * 65536 + (size_t)py * 256 * 64;
    const float*  b2a = b2 + ea * D_DIM + py * 256;
    const float*  b2b = b2 + eb * D_DIM + py * 256;

    const int r0 = tid >> 2, u0 = tid & 3, u1 = u0 + 4;
    const __half* hA0 = g_h + ((size_t)ea * B_TOK + pa_s[r0]) * H_DIM + u0 * 8;
    const __half* hA1 = g_h + ((size_t)ea * B_TOK + pa_s[r0]) * H_DIM + u1 * 8;
    const __half* hB0 = g_h + ((size_t)eb * B_TOK + pb_s[r0]) * H_DIM + u0 * 8;
    const __half* hB1 = g_h + ((size_t)eb * B_TOK + pb_s[r0]) * H_DIM + u1 * 8;
    const uint32_t sa0 = r0 * 128 + ((u0 ^ (r0 & 7)) << 4);
    const uint32_t sa1 = r0 * 128 + ((u1 ^ (r0 & 7)) << 4);

    float c[2][8][4];
#pragma unroll
    for (int mi = 0; mi < 2; mi++)
#pragma unroll
        for (int ni = 0; ni < 8; ni++)
#pragma unroll
            for (int q = 0; q < 4; q++) c[mi][ni][q] = 0.f;

    int ph[2] = {0, 0};

    if (tid == 0) { mbar_expect(mb[0], 32768); bulk_g2s(sb + ST_B, w2a, 32768, mb[0]); }
    cp16(sb + sa0, hA0); cp16(sb + sa1, hA1); cp_commit();

    for (int i = 0; i < 8; i++) {
        const int b = i & 1;
        cp_wait<0>();
        mbar_wait(mb[b], ph[b]); ph[b] ^= 1;
        __syncthreads();
        if (i + 1 < 8) {
            const int nsl = i + 1, nb = b ^ 1;
            const uint32_t st = sb + nb * ST_SZ;
            const __half* ws = (nsl < 4) ? (w2a + (size_t)nsl * 65536)
                                         : (w2b + (size_t)(nsl - 4) * 65536);
            if (tid == 0) { mbar_expect(mb[nb], 32768); bulk_g2s(st + ST_B, ws, 32768, mb[nb]); }
            const __half* s0 = (nsl < 4) ? (hA0 + nsl * 64) : (hB0 + (nsl - 4) * 64);
            const __half* s1 = (nsl < 4) ? (hA1 + nsl * 64) : (hB1 + (nsl - 4) * 64);
            cp16(st + sa0, s0);
            cp16(st + sa1, s1);
            cp_commit();
        }
        const uint32_t Ab = sb + b * ST_SZ;
        const uint32_t Bb = Ab + ST_B;
#pragma unroll
        for (int kk = 0; kk < 4; kk++) {
            uint32_t a[2][4], bf[4][4];
#pragma unroll
            for (int mi = 0; mi < 2; mi++) {
                int row = wm * 32 + mi * 16 + arl;
                int u   = 2 * kk + auo;
                ldsm4(a[mi], Ab + row * 128 + ((u ^ (row & 7)) << 4));
            }
#pragma unroll
            for (int q = 0; q < 4; q++) {
                int row = wn * 64 + q * 16 + brl;
                int u   = 2 * kk + buo;
                ldsm4(bf[q], Bb + row * 128 + ((u ^ (row & 7)) << 4));
            }
#pragma unroll
            for (int mi = 0; mi < 2; mi++)
#pragma unroll
                for (int ni = 0; ni < 8; ni++)
                    mma16(c[mi][ni], a[mi], &bf[ni >> 1][(ni & 1) * 2]);
        }
    }

#pragma unroll
    for (int mi = 0; mi < 2; mi++) {
#pragma unroll
        for (int h = 0; h < 2; h++) {
            int r = wm * 32 + mi * 16 + g + h * 8;
            if (r < mcount) {
                float wA = wA_s[r], wB = wB_s[r];
                float* dst = out + (size_t)tok_s[r] * D_DIM + py * 256;
#pragma unroll
                for (int ni = 0; ni < 8; ni++) {
                    int col = wn * 64 + ni * 8 + tg * 2;
                    float2 v = make_float2(
                        c[mi][ni][h * 2]     + wA * b2a[col]     + wB * b2b[col],
                        c[mi][ni][h * 2 + 1] + wA * b2a[col + 1] + wB * b2b[col + 1]);
                    *(float2*)(dst + col) = v;
                }
            }
        }
    }
}

// ---------------- launch ----------------
extern "C" void kernel_launch(void* const* d_in, const int* in_sizes, int n_in,
                              void* d_out, int out_size) {
    const float* x  = (const float*)d_in[0];
    const float* gw = (const float*)d_in[1];
    const float* gb = (const float*)d_in[2];
    const float* w1 = (const float*)d_in[3];
    const float* b1 = (const float*)d_in[4];
    const float* w2 = (const float*)d_in[5];
    const float* b2 = (const float*)d_in[6];
    float* out = (float*)d_out;

    static __half* w1h_ptr = nullptr;
    static __half* w2h_ptr = nullptr;
    if (!w1h_ptr) {
        cudaGetSymbolAddress((void**)&w1h_ptr, g_w1h);
        cudaGetSymbolAddress((void**)&w2h_ptr, g_w2h);
        cudaFuncSetAttribute(gate_kernel,
                             cudaFuncAttributeMaxDynamicSharedMemorySize, GATE_DYN);
        cudaFuncSetAttribute(expert1_kernel,
                             cudaFuncAttributeMaxDynamicSharedMemorySize, DYN_SMEM);
        cudaFuncSetAttribute(expert2_kernel,
                             cudaFuncAttributeMaxDynamicSharedMemorySize, DYN_SMEM);
    }

    prep_w_kernel<<<dim3(128, 1, 16), dim3(32, 8)>>>(w1, w2, w1h_ptr, w2h_ptr);
    gate_kernel<<<GATE_BLKS, 512, GATE_DYN>>>(x, gw, gb);
    expert1_kernel<<<dim3(E1_TILES), NTHR, DYN_SMEM>>>(b1);
    expert2_kernel<<<dim3(E2_TILES, 4), NTHR, DYN_SMEM>>>(b2, out);
}